// round 9
// baseline (speedup 1.0000x reference)
#include <cuda_runtime.h>
#include <math.h>

#define IDIM 128
#define HDIM 1024
#define NITER 4
#define NTOK 2048
#define NBLK 148            // one block per SM, balanced wave
#define NTHREADS 512        // 16 warps
#define TOKMAX 14           // blocks 0..123: 14 tokens, 124..147: 13
#define XPAD 384            // padded x_res (data at [127,254], zeros elsewhere)
#define WST_STRIDE 33       // float4 stride per staged weight row (conflict-free)
#define HROW 264            // h row stride in floats

typedef unsigned long long ull;

__device__ float g_psum[NBLK];
__device__ float g_pcnt[NBLK];

// ---- packed fp32x2 helpers ----
__device__ __forceinline__ ull pk(float lo, float hi) {
    ull r; asm("mov.b64 %0, {%1, %2};" : "=l"(r) : "f"(lo), "f"(hi)); return r;
}
__device__ __forceinline__ void fma2(ull& acc, ull a, ull b) {
    asm("fma.rn.f32x2 %0, %1, %2, %3;" : "=l"(acc) : "l"(a), "l"(b), "l"(acc));
}
__device__ __forceinline__ float2 upk(ull v) {
    float2 r; asm("mov.b64 {%0, %1}, %2;" : "=f"(r.x), "=f"(r.y) : "l"(v)); return r;
}
// 16B shared load -> two aligned f32x2 pairs (no pack MOVs)
__device__ __forceinline__ void lds2(ull& a, ull& b, unsigned addr) {
    asm("ld.shared.v2.b64 {%0, %1}, [%2];" : "=l"(a), "=l"(b) : "r"(addr));
}
__device__ __forceinline__ unsigned s2u(const void* p) {
    unsigned a;
    asm("{ .reg .u64 t; cvta.to.shared.u64 t, %1; cvt.u32.u64 %0, t; }"
        : "=r"(a) : "l"(p));
    return a;
}

struct __align__(16) Smem {
    float4 wst[IDIM * WST_STRIDE];     // 67584 B
    float  xp[TOKMAX][XPAD];           // 21504 B  padded x_res
    float  xps[TOKMAX][XPAD];          // 21504 B  shadow: xps[i] = xp[i+1]
    float  xa[TOKMAX][IDIM];           // 7168 B
    float  h[TOKMAX][HROW];            // 14784 B
    float  yres[TOKMAX][IDIM];         // 7168 B
    float  red[16];
    float  red2[16];
    unsigned char ymask[TOKMAX][IDIM]; // 1792 B
};

extern __shared__ unsigned char smem_raw[];

__global__ void __launch_bounds__(NTHREADS, 1)
net_main_kernel(const float* __restrict__ x, const float* __restrict__ y,
                const float* __restrict__ w1, const float* __restrict__ b1,
                const float* __restrict__ w2, const float* __restrict__ b2)
{
    Smem& sm = *reinterpret_cast<Smem*>(smem_raw);
    const int tid  = threadIdx.x;
    const int lane = tid & 31;
    const int wid  = tid >> 5;
    const int blk  = blockIdx.x;
    const int tcnt = (blk < 124) ? 14 : 13;
    const int tok0 = (blk < 124) ? blk * 14 : 124 * 14 + (blk - 124) * 13;

    // ---- zero padded x buffers ----
    for (int e = tid; e < TOKMAX * XPAD; e += NTHREADS) {
        (&sm.xp[0][0])[e]  = 0.f;
        (&sm.xps[0][0])[e] = 0.f;
    }
    __syncthreads();

    // ---- load x (both copies), y, mask; count unmasked ----
    float cnt = 0.f;
    for (int e = tid; e < tcnt * IDIM; e += NTHREADS) {
        int m = e >> 7, d = e & 127;
        float xv = x[(tok0 + m) * IDIM + d];
        sm.xp[m][127 + d]  = xv;
        sm.xps[m][126 + d] = xv;           // shadow shifted by one
        float yv = y[(tok0 + m) * IDIM + d];
        sm.yres[m][d] = yv;
        unsigned char msk = (yv == 10000.0f) ? 1 : 0;
        sm.ymask[m][d] = msk;
        cnt += msk ? 0.f : 1.f;
    }

    float sqacc = 0.f;
    const int o = tid & 127;
    const int g = tid >> 7;

    int  slot[4];
    bool sv[4];
    #pragma unroll
    for (int t = 0; t < 4; ++t) { slot[t] = g + 4 * t; sv[t] = slot[t] < tcnt; }

    const unsigned wrow_a = s2u(&sm.wst[o * WST_STRIDE]);
    unsigned xa_a[4], h_a[4];
    #pragma unroll
    for (int t = 0; t < 4; ++t) {
        int s = sv[t] ? slot[t] : 0;
        xa_a[t] = s2u(&sm.xa[s][0]);
        h_a[t]  = s2u(&sm.h[s][0]);
    }

    const float4* wg2 = reinterpret_cast<const float4*>(w2);
    float4 v[8];   // staging prefetch registers

    for (int it = 0; it < NITER; ++it) {
        __syncthreads();   // S0: yres/xp/xps stable, wst free

        // ================= Phase A: per-warp token pipeline (FFMA2) =========
        if (wid < tcnt) {
            const int m = wid;
            float* xpm  = sm.xp[m];
            float* xpsm = sm.xps[m];
            const float* ym = sm.yres[m];
            const unsigned aA = s2u(xpm);
            const unsigned aB = s2u(xpsm);
            const unsigned aY = s2u(ym);

            // ||y_res||
            float ny2 = 0.f;
            #pragma unroll
            for (int j = 0; j < 4; ++j) { float vv = ym[lane + 32 * j]; ny2 += vv * vv; }
            #pragma unroll
            for (int off = 16; off; off >>= 1) ny2 += __shfl_xor_sync(~0u, ny2, off);
            float ny = sqrtf(ny2);

            // banded correlation, fully packed: lane shifts s = 4*lane+128*b+j
            ull num2[8], dn2[8];
            #pragma unroll
            for (int k = 0; k < 8; ++k) { num2[k] = 0ull; dn2[k] = 0ull; }
            #pragma unroll
            for (int b = 0; b < 2; ++b) {
                const int q0 = lane + 32 * b;
                const int k0 = 4 * b;
                ull Alo, Ahi, Blo, Bhi;
                lds2(Alo, Ahi, aA + q0 * 16);
                lds2(Blo, Bhi, aB + q0 * 16);
                #pragma unroll 8
                for (int d4 = 0; d4 < 32; ++d4) {
                    ull ylo, yhi, AnL, AnH, BnL, BnH;
                    lds2(ylo, yhi, aY + d4 * 16);
                    lds2(AnL, AnH, aA + (q0 + d4 + 1) * 16);
                    lds2(BnL, BnH, aB + (q0 + d4 + 1) * 16);
                    // j=0: (x0,x1)=Alo, (x2,x3)=Ahi
                    fma2(num2[k0+0], ylo, Alo); fma2(num2[k0+0], yhi, Ahi);
                    fma2(dn2[k0+0],  Alo, Alo); fma2(dn2[k0+0],  Ahi, Ahi);
                    // j=1: (x1,x2)=Blo, (x3,x4)=Bhi
                    fma2(num2[k0+1], ylo, Blo); fma2(num2[k0+1], yhi, Bhi);
                    fma2(dn2[k0+1],  Blo, Blo); fma2(dn2[k0+1],  Bhi, Bhi);
                    // j=2: (x2,x3)=Ahi, (x4,x5)=AnL
                    fma2(num2[k0+2], ylo, Ahi); fma2(num2[k0+2], yhi, AnL);
                    fma2(dn2[k0+2],  Ahi, Ahi); fma2(dn2[k0+2],  AnL, AnL);
                    // j=3: (x3,x4)=Bhi, (x5,x6)=BnL
                    fma2(num2[k0+3], ylo, Bhi); fma2(num2[k0+3], yhi, BnL);
                    fma2(dn2[k0+3],  Bhi, Bhi); fma2(dn2[k0+3],  BnL, BnL);
                    Alo = AnL; Ahi = AnH; Blo = BnL; Bhi = BnH;
                }
            }

            // first-max (ascending s within lane), then warp first-max
            float best = -INFINITY; int bs = 0x7fffffff;
            #pragma unroll
            for (int b = 0; b < 2; ++b)
            #pragma unroll
            for (int j = 0; j < 4; ++j) {
                int s = 4 * lane + 128 * b + j;
                if (s < 255) {
                    int kk = 4 * b + j;
                    float2 nn = upk(num2[kk]);
                    float2 qq = upk(dn2[kk]);
                    float numv = nn.x + nn.y;
                    float dnv  = qq.x + qq.y;
                    float den = ny * sqrtf(dnv);
                    float sim = (den == 0.f) ? 0.f : numv / den;
                    if (sim > best) { best = sim; bs = s; }
                }
            }
            #pragma unroll
            for (int off = 16; off; off >>= 1) {
                float ob = __shfl_xor_sync(~0u, best, off);
                int   os = __shfl_xor_sync(~0u, bs,   off);
                if (ob > best || (ob == best && os < bs)) { best = ob; bs = os; }
            }
            const int idx = bs;

            // softmax attention: z = x_aug * y_res
            float xav[4], z[4];
            float zmax = -INFINITY;
            #pragma unroll
            for (int j = 0; j < 4; ++j) {
                int d = lane + 32 * j;
                xav[j] = xpm[idx + d];
                z[j]   = xav[j] * ym[d];
                zmax   = fmaxf(zmax, z[j]);
            }
            #pragma unroll
            for (int off = 16; off; off >>= 1) zmax = fmaxf(zmax, __shfl_xor_sync(~0u, zmax, off));
            float es = 0.f, e[4];
            #pragma unroll
            for (int j = 0; j < 4; ++j) { e[j] = expf(z[j] - zmax); es += e[j]; }
            #pragma unroll
            for (int off = 16; off; off >>= 1) es += __shfl_xor_sync(~0u, es, off);
            #pragma unroll
            for (int j = 0; j < 4; ++j) {
                int d = lane + 32 * j;
                sm.xa[m][d] = xav[j] * (e[j] / es);
            }
            __syncwarp();
            // reverse shift: x_res[d] -= x_attn[d + 127 - idx]; update both copies
            #pragma unroll
            for (int j = 0; j < 4; ++j) {
                int d = lane + 32 * j;
                int src = d + 127 - idx;
                float xe = (src >= 0 && src < 128) ? sm.xa[m][src] : 0.f;
                xpm[127 + d]  -= xe;
                xpsm[126 + d] -= xe;
            }
        }

        // prefetch w1 chunk0 (arrives during barrier / early staging)
        {
            const float4* wg = reinterpret_cast<const float4*>(
                w1 + (size_t)(it * 256) * IDIM);
            #pragma unroll
            for (int r = 0; r < 8; ++r) v[r] = wg[tid + r * 512];
        }
        __syncthreads();   // S1: xa ready, xp done

        // ================= Phase B: h = x_attn @ W1_slice^T + b1 ===========
        ull accB[4];
        #pragma unroll
        for (int chunk = 0; chunk < 2; ++chunk) {
            // store staged regs -> wst
            #pragma unroll
            for (int r = 0; r < 8; ++r) {
                int j = tid + r * 512;
                sm.wst[(j >> 5) * WST_STRIDE + (j & 31)] = v[r];
            }
            __syncthreads();
            // prefetch next tile: chunk0 -> w1 chunk1; chunk1 -> w2 chunk0
            if (chunk == 0) {
                const float4* wg = reinterpret_cast<const float4*>(
                    w1 + (size_t)(it * 256 + 128) * IDIM);
                #pragma unroll
                for (int r = 0; r < 8; ++r) v[r] = wg[tid + r * 512];
            } else {
                #pragma unroll
                for (int r = 0; r < 8; ++r) {
                    int j = tid + r * 512;
                    v[r] = wg2[(size_t)(j >> 5) * (HDIM / 4) + it * 64 + (j & 31)];
                }
            }

            float bv = b1[it * 256 + chunk * 128 + o];
            accB[0] = pk(bv, 0.f); accB[1] = pk(bv, 0.f);
            accB[2] = pk(bv, 0.f); accB[3] = pk(bv, 0.f);
            #pragma unroll 8
            for (int d4 = 0; d4 < 32; ++d4) {
                ull w01, w23;
                lds2(w01, w23, wrow_a + d4 * 16);
                #pragma unroll
                for (int t = 0; t < 4; ++t) {
                    ull x01, x23;
                    lds2(x01, x23, xa_a[t] + d4 * 16);
                    fma2(accB[t], w01, x01);
                    fma2(accB[t], w23, x23);
                }
            }
            #pragma unroll
            for (int t = 0; t < 4; ++t) {
                if (sv[t]) {
                    float2 a = upk(accB[t]);
                    sm.h[slot[t]][chunk * 128 + o] = a.x + a.y;
                }
            }
            __syncthreads();
        }

        // ================= Phase C: y_ele = h @ W2_slice^T + b2 ============
        float b2v = b2[o];
        ull accc[4];
        accc[0] = pk(b2v, 0.f); accc[1] = pk(b2v, 0.f);
        accc[2] = pk(b2v, 0.f); accc[3] = pk(b2v, 0.f);
        #pragma unroll
        for (int chunk = 0; chunk < 2; ++chunk) {
            #pragma unroll
            for (int r = 0; r < 8; ++r) {
                int j = tid + r * 512;
                sm.wst[(j >> 5) * WST_STRIDE + (j & 31)] = v[r];
            }
            __syncthreads();
            if (chunk == 0) {   // prefetch w2 chunk1
                #pragma unroll
                for (int r = 0; r < 8; ++r) {
                    int j = tid + r * 512;
                    v[r] = wg2[(size_t)(j >> 5) * (HDIM / 4) + it * 64 + 32 + (j & 31)];
                }
            }

            const unsigned hoff = chunk * 512;
            #pragma unroll 8
            for (int c4 = 0; c4 < 32; ++c4) {
                ull w01, w23;
                lds2(w01, w23, wrow_a + c4 * 16);
                #pragma unroll
                for (int t = 0; t < 4; ++t) {
                    ull h01, h23;
                    lds2(h01, h23, h_a[t] + hoff + c4 * 16);
                    fma2(accc[t], w01, h01);
                    fma2(accc[t], w23, h23);
                }
            }
            if (chunk == 0) __syncthreads();   // before restaging wst
        }

        // ---- masked squared error + y_res update ----
        #pragma unroll
        for (int t = 0; t < 4; ++t) {
            if (sv[t]) {
                int m = slot[t];
                float2 c2 = upk(accc[t]);
                float ye = c2.x + c2.y;
                float yr = sm.yres[m][o];
                if (!sm.ymask[m][o]) { float dd = ye - yr; sqacc += dd * dd; }
                sm.yres[m][o] = yr - ye;
            }
        }
        // loop-top S0 orders these writes before next phase A / staging
    }

    // ---- block reduction ----
    #pragma unroll
    for (int off = 16; off; off >>= 1) {
        sqacc += __shfl_xor_sync(~0u, sqacc, off);
        cnt   += __shfl_xor_sync(~0u, cnt,   off);
    }
    if (lane == 0) { sm.red[wid] = sqacc; sm.red2[wid] = cnt; }
    __syncthreads();
    if (tid == 0) {
        float s = 0.f, c = 0.f;
        #pragma unroll
        for (int w = 0; w < 16; ++w) { s += sm.red[w]; c += sm.red2[w]; }
        g_psum[blk] = s;
        g_pcnt[blk] = c;
    }
}

__global__ void net_final_kernel(float* __restrict__ out)
{
    __shared__ float ss[256];
    __shared__ float sc[256];
    int t = threadIdx.x;
    ss[t] = (t < NBLK) ? g_psum[t] : 0.f;
    sc[t] = (t < NBLK) ? g_pcnt[t] : 0.f;
    __syncthreads();
    for (int off = 128; off; off >>= 1) {
        if (t < off) { ss[t] += ss[t + off]; sc[t] += sc[t + off]; }
        __syncthreads();
    }
    if (t == 0) out[0] = ss[0] / (4.0f * sc[0]);
}

extern "C" void kernel_launch(void* const* d_in, const int* in_sizes, int n_in,
                              void* d_out, int out_size)
{
    (void)in_sizes; (void)n_in; (void)out_size;
    const float* x  = (const float*)d_in[0];
    const float* y  = (const float*)d_in[1];
    const float* w1 = (const float*)d_in[2];
    const float* b1 = (const float*)d_in[3];
    const float* w2 = (const float*)d_in[4];
    const float* b2 = (const float*)d_in[5];
    float* out = (float*)d_out;

    cudaFuncSetAttribute(net_main_kernel,
                         cudaFuncAttributeMaxDynamicSharedMemorySize,
                         (int)sizeof(Smem));
    net_main_kernel<<<NBLK, NTHREADS, sizeof(Smem)>>>(x, y, w1, b1, w2, b2);
    net_final_kernel<<<1, 256>>>(out);
}

// round 10
// speedup vs baseline: 1.0058x; 1.0058x over previous
#include <cuda_runtime.h>
#include <math.h>

#define IDIM 128
#define HDIM 1024
#define NITER 4
#define NTOK 2048
#define NBLK 148            // one block per SM, balanced wave
#define NTHREADS 512        // 16 warps
#define TOKMAX 14           // blocks 0..123: 14 tokens, 124..147: 13
#define XPAD 384            // padded x_res (data at [127,254], zeros elsewhere)
#define WST_STRIDE 33       // float4 stride per staged weight row (conflict-free)
#define HROW 264            // h row stride in floats

typedef unsigned long long ull;

__device__ float g_psum[NBLK];
__device__ float g_pcnt[NBLK];
__device__ int   g_cnt = 0;          // last-block ticket; reset by last block

// ---- packed fp32x2 helpers ----
__device__ __forceinline__ ull pk(float lo, float hi) {
    ull r; asm("mov.b64 %0, {%1, %2};" : "=l"(r) : "f"(lo), "f"(hi)); return r;
}
__device__ __forceinline__ void fma2(ull& acc, ull a, ull b) {
    asm("fma.rn.f32x2 %0, %1, %2, %3;" : "=l"(acc) : "l"(a), "l"(b), "l"(acc));
}
__device__ __forceinline__ float2 upk(ull v) {
    float2 r; asm("mov.b64 {%0, %1}, %2;" : "=f"(r.x), "=f"(r.y) : "l"(v)); return r;
}
__device__ __forceinline__ void lds2(ull& a, ull& b, unsigned addr) {
    asm("ld.shared.v2.b64 {%0, %1}, [%2];" : "=l"(a), "=l"(b) : "r"(addr));
}
__device__ __forceinline__ unsigned s2u(const void* p) {
    unsigned a;
    asm("{ .reg .u64 t; cvta.to.shared.u64 t, %1; cvt.u32.u64 %0, t; }"
        : "=r"(a) : "l"(p));
    return a;
}

struct __align__(16) Smem {
    float4 wstA[IDIM * WST_STRIDE];    // 67584 B  staged weights, buffer A
    float4 wstB[IDIM * WST_STRIDE];    // 67584 B  staged weights, buffer B
    float  xp[TOKMAX][XPAD];           // 21504 B  padded x_res
    float  xps[TOKMAX][XPAD];          // 21504 B  shadow: xps[i] = xp[i+1]
    float  xa[TOKMAX][IDIM];           // 7168 B
    float  h[TOKMAX][HROW];            // 14784 B
    float  yres[TOKMAX][IDIM];         // 7168 B
    float  red[16];
    float  red2[16];
    float  fred[256];                  // final-reduction scratch (last block)
    float  fred2[256];
    int    islast;
    unsigned char ymask[TOKMAX][IDIM]; // 1792 B
};

extern __shared__ unsigned char smem_raw[];

__global__ void __launch_bounds__(NTHREADS, 1)
net_main_kernel(const float* __restrict__ x, const float* __restrict__ y,
                const float* __restrict__ w1, const float* __restrict__ b1,
                const float* __restrict__ w2, const float* __restrict__ b2,
                float* __restrict__ out)
{
    Smem& sm = *reinterpret_cast<Smem*>(smem_raw);
    const int tid  = threadIdx.x;
    const int lane = tid & 31;
    const int wid  = tid >> 5;
    const int blk  = blockIdx.x;
    const int tcnt = (blk < 124) ? 14 : 13;
    const int tok0 = (blk < 124) ? blk * 14 : 124 * 14 + (blk - 124) * 13;

    // ---- zero padded x buffers ----
    for (int e = tid; e < TOKMAX * XPAD; e += NTHREADS) {
        (&sm.xp[0][0])[e]  = 0.f;
        (&sm.xps[0][0])[e] = 0.f;
    }
    __syncthreads();

    // ---- load x (both copies), y, mask; count unmasked ----
    float cnt = 0.f;
    for (int e = tid; e < tcnt * IDIM; e += NTHREADS) {
        int m = e >> 7, d = e & 127;
        float xv = x[(tok0 + m) * IDIM + d];
        sm.xp[m][127 + d]  = xv;
        sm.xps[m][126 + d] = xv;
        float yv = y[(tok0 + m) * IDIM + d];
        sm.yres[m][d] = yv;
        unsigned char msk = (yv == 10000.0f) ? 1 : 0;
        sm.ymask[m][d] = msk;
        cnt += msk ? 0.f : 1.f;
    }

    float sqacc = 0.f;
    const int o = tid & 127;
    const int g = tid >> 7;

    int  slot[4];
    bool sv[4];
    #pragma unroll
    for (int t = 0; t < 4; ++t) { slot[t] = g + 4 * t; sv[t] = slot[t] < tcnt; }

    const unsigned wrowA = s2u(&sm.wstA[o * WST_STRIDE]);
    const unsigned wrowB = s2u(&sm.wstB[o * WST_STRIDE]);
    unsigned xa_a[4], h_a[4];
    #pragma unroll
    for (int t = 0; t < 4; ++t) {
        int s = sv[t] ? slot[t] : 0;
        xa_a[t] = s2u(&sm.xa[s][0]);
        h_a[t]  = s2u(&sm.h[s][0]);
    }

    const float4* wg2 = reinterpret_cast<const float4*>(w2);
    float4 v[8];
    const int jrow = tid >> 5;            // constant per thread: j = tid + r*512
    // (j>>5, j&31) for j = tid + r*512: row = jrow + r*16, col = tid & 31
    const int jcol = tid & 31;

    for (int it = 0; it < NITER; ++it) {
        __syncthreads();   // S0: yres/xp/xps stable; all prior wst reads done

        // issue LDG of w1 chunk0 early (hides under phase A)
        {
            const float4* wg = reinterpret_cast<const float4*>(
                w1 + (size_t)(it * 256) * IDIM);
            #pragma unroll
            for (int r = 0; r < 8; ++r) v[r] = wg[tid + r * 512];
        }

        // ================= Phase A: per-warp token pipeline (FFMA2) =========
        if (wid < tcnt) {
            const int m = wid;
            float* xpm  = sm.xp[m];
            float* xpsm = sm.xps[m];
            const float* ym = sm.yres[m];
            const unsigned aA = s2u(xpm);
            const unsigned aB = s2u(xpsm);
            const unsigned aY = s2u(ym);

            float ny2 = 0.f;
            #pragma unroll
            for (int j = 0; j < 4; ++j) { float vv = ym[lane + 32 * j]; ny2 += vv * vv; }
            #pragma unroll
            for (int off = 16; off; off >>= 1) ny2 += __shfl_xor_sync(~0u, ny2, off);
            float ny = sqrtf(ny2);

            ull num2[8], dn2[8];
            #pragma unroll
            for (int k = 0; k < 8; ++k) { num2[k] = 0ull; dn2[k] = 0ull; }
            #pragma unroll
            for (int b = 0; b < 2; ++b) {
                const int q0 = lane + 32 * b;
                const int k0 = 4 * b;
                ull Alo, Ahi, Blo, Bhi;
                lds2(Alo, Ahi, aA + q0 * 16);
                lds2(Blo, Bhi, aB + q0 * 16);
                #pragma unroll 8
                for (int d4 = 0; d4 < 32; ++d4) {
                    ull ylo, yhi, AnL, AnH, BnL, BnH;
                    lds2(ylo, yhi, aY + d4 * 16);
                    lds2(AnL, AnH, aA + (q0 + d4 + 1) * 16);
                    lds2(BnL, BnH, aB + (q0 + d4 + 1) * 16);
                    fma2(num2[k0+0], ylo, Alo); fma2(num2[k0+0], yhi, Ahi);
                    fma2(dn2[k0+0],  Alo, Alo); fma2(dn2[k0+0],  Ahi, Ahi);
                    fma2(num2[k0+1], ylo, Blo); fma2(num2[k0+1], yhi, Bhi);
                    fma2(dn2[k0+1],  Blo, Blo); fma2(dn2[k0+1],  Bhi, Bhi);
                    fma2(num2[k0+2], ylo, Ahi); fma2(num2[k0+2], yhi, AnL);
                    fma2(dn2[k0+2],  Ahi, Ahi); fma2(dn2[k0+2],  AnL, AnL);
                    fma2(num2[k0+3], ylo, Bhi); fma2(num2[k0+3], yhi, BnL);
                    fma2(dn2[k0+3],  Bhi, Bhi); fma2(dn2[k0+3],  BnL, BnL);
                    Alo = AnL; Ahi = AnH; Blo = BnL; Bhi = BnH;
                }
            }

            float best = -INFINITY; int bs = 0x7fffffff;
            #pragma unroll
            for (int b = 0; b < 2; ++b)
            #pragma unroll
            for (int j = 0; j < 4; ++j) {
                int s = 4 * lane + 128 * b + j;
                if (s < 255) {
                    int kk = 4 * b + j;
                    float2 nn = upk(num2[kk]);
                    float2 qq = upk(dn2[kk]);
                    float numv = nn.x + nn.y;
                    float dnv  = qq.x + qq.y;
                    float den = ny * sqrtf(dnv);
                    float sim = (den == 0.f) ? 0.f : numv / den;
                    if (sim > best) { best = sim; bs = s; }
                }
            }
            #pragma unroll
            for (int off = 16; off; off >>= 1) {
                float ob = __shfl_xor_sync(~0u, best, off);
                int   os = __shfl_xor_sync(~0u, bs,   off);
                if (ob > best || (ob == best && os < bs)) { best = ob; bs = os; }
            }
            const int idx = bs;

            float xav[4], z[4];
            float zmax = -INFINITY;
            #pragma unroll
            for (int j = 0; j < 4; ++j) {
                int d = lane + 32 * j;
                xav[j] = xpm[idx + d];
                z[j]   = xav[j] * ym[d];
                zmax   = fmaxf(zmax, z[j]);
            }
            #pragma unroll
            for (int off = 16; off; off >>= 1) zmax = fmaxf(zmax, __shfl_xor_sync(~0u, zmax, off));
            float es = 0.f, e[4];
            #pragma unroll
            for (int j = 0; j < 4; ++j) { e[j] = expf(z[j] - zmax); es += e[j]; }
            #pragma unroll
            for (int off = 16; off; off >>= 1) es += __shfl_xor_sync(~0u, es, off);
            #pragma unroll
            for (int j = 0; j < 4; ++j) {
                int d = lane + 32 * j;
                sm.xa[m][d] = xav[j] * (e[j] / es);
            }
            __syncwarp();
            #pragma unroll
            for (int j = 0; j < 4; ++j) {
                int d = lane + 32 * j;
                int src = d + 127 - idx;
                float xe = (src >= 0 && src < 128) ? sm.xa[m][src] : 0.f;
                xpm[127 + d]  -= xe;
                xpsm[126 + d] -= xe;
            }
        }

        // STS w1c0 -> bufA (before S1 so S1 covers both xa and bufA)
        #pragma unroll
        for (int r = 0; r < 8; ++r)
            sm.wstA[(jrow + r * 16) * WST_STRIDE + jcol] = v[r];
        __syncthreads();   // S1

        // ================= Phase B =================
        ull accB[4];
        float b2v = b2[o];
        ull accc[4];
        accc[0] = pk(b2v, 0.f); accc[1] = pk(b2v, 0.f);
        accc[2] = pk(b2v, 0.f); accc[3] = pk(b2v, 0.f);

        // ---- B chunk0: compute from bufA; LDG w1c1; STS -> bufB ----
        {
            const float4* wg = reinterpret_cast<const float4*>(
                w1 + (size_t)(it * 256 + 128) * IDIM);
            #pragma unroll
            for (int r = 0; r < 8; ++r) v[r] = wg[tid + r * 512];

            float bv = b1[it * 256 + o];
            accB[0] = pk(bv, 0.f); accB[1] = pk(bv, 0.f);
            accB[2] = pk(bv, 0.f); accB[3] = pk(bv, 0.f);
            #pragma unroll 8
            for (int d4 = 0; d4 < 32; ++d4) {
                ull w01, w23;
                lds2(w01, w23, wrowA + d4 * 16);
                #pragma unroll
                for (int t = 0; t < 4; ++t) {
                    ull x01, x23;
                    lds2(x01, x23, xa_a[t] + d4 * 16);
                    fma2(accB[t], w01, x01);
                    fma2(accB[t], w23, x23);
                }
            }
            #pragma unroll
            for (int t = 0; t < 4; ++t) {
                if (sv[t]) {
                    float2 a = upk(accB[t]);
                    sm.h[slot[t]][o] = a.x + a.y;
                }
            }
            #pragma unroll
            for (int r = 0; r < 8; ++r)
                sm.wstB[(jrow + r * 16) * WST_STRIDE + jcol] = v[r];
        }
        __syncthreads();   // SB1

        // ---- B chunk1: compute from bufB; LDG w2c0; STS -> bufA ----
        {
            #pragma unroll
            for (int r = 0; r < 8; ++r) {
                int j = tid + r * 512;
                v[r] = wg2[(size_t)(j >> 5) * (HDIM / 4) + it * 64 + (j & 31)];
            }
            float bv = b1[it * 256 + 128 + o];
            accB[0] = pk(bv, 0.f); accB[1] = pk(bv, 0.f);
            accB[2] = pk(bv, 0.f); accB[3] = pk(bv, 0.f);
            #pragma unroll 8
            for (int d4 = 0; d4 < 32; ++d4) {
                ull w01, w23;
                lds2(w01, w23, wrowB + d4 * 16);
                #pragma unroll
                for (int t = 0; t < 4; ++t) {
                    ull x01, x23;
                    lds2(x01, x23, xa_a[t] + d4 * 16);
                    fma2(accB[t], w01, x01);
                    fma2(accB[t], w23, x23);
                }
            }
            #pragma unroll
            for (int t = 0; t < 4; ++t) {
                if (sv[t]) {
                    float2 a = upk(accB[t]);
                    sm.h[slot[t]][128 + o] = a.x + a.y;
                }
            }
            #pragma unroll
            for (int r = 0; r < 8; ++r)
                sm.wstA[(jrow + r * 16) * WST_STRIDE + jcol] = v[r];
        }
        __syncthreads();   // SB2

        // ---- C chunk0: compute from bufA; LDG w2c1; STS -> bufB ----
        {
            #pragma unroll
            for (int r = 0; r < 8; ++r) {
                int j = tid + r * 512;
                v[r] = wg2[(size_t)(j >> 5) * (HDIM / 4) + it * 64 + 32 + (j & 31)];
            }
            #pragma unroll 8
            for (int c4 = 0; c4 < 32; ++c4) {
                ull w01, w23;
                lds2(w01, w23, wrowA + c4 * 16);
                #pragma unroll
                for (int t = 0; t < 4; ++t) {
                    ull h01, h23;
                    lds2(h01, h23, h_a[t] + c4 * 16);
                    fma2(accc[t], w01, h01);
                    fma2(accc[t], w23, h23);
                }
            }
            #pragma unroll
            for (int r = 0; r < 8; ++r)
                sm.wstB[(jrow + r * 16) * WST_STRIDE + jcol] = v[r];
        }
        __syncthreads();   // SB3

        // ---- C chunk1: compute from bufB ----
        #pragma unroll 8
        for (int c4 = 0; c4 < 32; ++c4) {
            ull w01, w23;
            lds2(w01, w23, wrowB + c4 * 16);
            #pragma unroll
            for (int t = 0; t < 4; ++t) {
                ull h01, h23;
                lds2(h01, h23, h_a[t] + 512 + c4 * 16);
                fma2(accc[t], w01, h01);
                fma2(accc[t], w23, h23);
            }
        }

        // ---- masked squared error + y_res update ----
        #pragma unroll
        for (int t = 0; t < 4; ++t) {
            if (sv[t]) {
                int m = slot[t];
                float2 c2 = upk(accc[t]);
                float ye = c2.x + c2.y;
                float yr = sm.yres[m][o];
                if (!sm.ymask[m][o]) { float dd = ye - yr; sqacc += dd * dd; }
                sm.yres[m][o] = yr - ye;
            }
        }
        // loop-top S0 orders these writes before next phase A / bufA reuse
    }

    // ---- block reduction ----
    #pragma unroll
    for (int off = 16; off; off >>= 1) {
        sqacc += __shfl_xor_sync(~0u, sqacc, off);
        cnt   += __shfl_xor_sync(~0u, cnt,   off);
    }
    if (lane == 0) { sm.red[wid] = sqacc; sm.red2[wid] = cnt; }
    __syncthreads();
    if (tid == 0) {
        float s = 0.f, c = 0.f;
        #pragma unroll
        for (int w = 0; w < 16; ++w) { s += sm.red[w]; c += sm.red2[w]; }
        g_psum[blk] = s;
        g_pcnt[blk] = c;
        __threadfence();
        int ticket = atomicAdd(&g_cnt, 1);
        __threadfence();
        sm.islast = (ticket == NBLK - 1) ? 1 : 0;
    }
    __syncthreads();

    // ---- last block: deterministic global reduction (same order as before) ----
    if (sm.islast) {
        int t = tid;
        if (t < 256) {
            sm.fred[t]  = (t < NBLK) ? g_psum[t] : 0.f;
            sm.fred2[t] = (t < NBLK) ? g_pcnt[t] : 0.f;
        }
        __syncthreads();
        for (int off = 128; off; off >>= 1) {
            if (t < off) { sm.fred[t] += sm.fred[t + off]; sm.fred2[t] += sm.fred2[t + off]; }
            __syncthreads();
        }
        if (t == 0) {
            out[0] = sm.fred[0] / (4.0f * sm.fred2[0]);
            g_cnt = 0;   // reset for next graph replay
        }
    }
}

extern "C" void kernel_launch(void* const* d_in, const int* in_sizes, int n_in,
                              void* d_out, int out_size)
{
    (void)in_sizes; (void)n_in; (void)out_size;
    const float* x  = (const float*)d_in[0];
    const float* y  = (const float*)d_in[1];
    const float* w1 = (const float*)d_in[2];
    const float* b1 = (const float*)d_in[3];
    const float* w2 = (const float*)d_in[4];
    const float* b2 = (const float*)d_in[5];
    float* out = (float*)d_out;

    cudaFuncSetAttribute(net_main_kernel,
                         cudaFuncAttributeMaxDynamicSharedMemorySize,
                         (int)sizeof(Smem));
    net_main_kernel<<<NBLK, NTHREADS, sizeof(Smem)>>>(x, y, w1, b1, w2, b2, out);
}